// round 1
// baseline (speedup 1.0000x reference)
#include <cuda_runtime.h>

#define HIDDEN 2048
#define BATCH 16384
#define NUM_OPS 3

#define BM 128
#define BN 128
#define BK 16
#define THREADS 256

// Scratch (device globals: allocation-free kernel_launch per harness rules)
__device__ int   g_counts[NUM_OPS];
__device__ int   g_idx[NUM_OPS * BATCH];
__device__ float g_h[(long long)BATCH * HIDDEN];   // layer-1 activations, original row order

__global__ void zero_counts_kernel() {
    if (threadIdx.x < NUM_OPS) g_counts[threadIdx.x] = 0;
}

__global__ void bucket_kernel(const int* __restrict__ chosen) {
    int i = blockIdx.x * blockDim.x + threadIdx.x;
    if (i < BATCH) {
        int e = chosen[i];
        int pos = atomicAdd(&g_counts[e], 1);
        g_idx[e * BATCH + pos] = i;
    }
}

// C[row] = relu( A[row] @ W[e] + bias[e] ) for rows in bucket e.
// A is indexed through g_idx (gather); output scattered back to original row ids.
__global__ __launch_bounds__(THREADS, 2)
void ffn_gemm_kernel(const float* __restrict__ A,     // [BATCH, HIDDEN]
                     const float* __restrict__ W,     // [NUM_OPS, HIDDEN, HIDDEN] (h-major, k contiguous)
                     const float* __restrict__ bias,  // [NUM_OPS, HIDDEN]
                     float* __restrict__ Out)         // [BATCH, HIDDEN]
{
    const int e   = blockIdx.z;
    const int cnt = g_counts[e];
    const int m0  = blockIdx.y * BM;
    if (m0 >= cnt) return;                 // bucket smaller than this tile
    const int n0  = blockIdx.x * BN;
    const int* idx = g_idx + e * BATCH;
    const float* We = W + (long long)e * HIDDEN * HIDDEN;

    __shared__ float As[BK][BM];           // transposed A tile: As[k][m]
    __shared__ float Bs[BK][BN];           // Bs[k][n]
    __shared__ int   rows[BM];

    const int tid = threadIdx.x;

    if (tid < BM) {
        int mi = m0 + tid;
        rows[tid] = idx[(mi < cnt) ? mi : 0];
    }
    __syncthreads();

    // Compute-thread mapping: warp = 8 m-groups x 4 n-groups (conflict-friendly)
    const int lane   = tid & 31;
    const int warp   = tid >> 5;
    const int warp_m = warp & 1;           // 0..1
    const int warp_n = warp >> 1;          // 0..3
    const int mg     = lane & 7;           // 0..7
    const int ng     = lane >> 3;          // 0..3
    const int tm     = warp_m * 64 + mg * 8;   // row offset in tile
    const int tn     = warp_n * 32 + ng * 8;   // col offset in tile

    float acc[8][8];
    #pragma unroll
    for (int i = 0; i < 8; i++)
        #pragma unroll
        for (int j = 0; j < 8; j++) acc[i][j] = 0.f;

    // A staging: 512 float4 per tile, 2 per thread
    const int ar0 = tid >> 2;              // 0..63
    const int ac4 = (tid & 3) * 4;         // 0,4,8,12
    // B staging: 512 float4 per tile, 2 per thread
    const int br0 = tid >> 5;              // 0..7
    const int bc  = (tid & 31) * 4;        // 0..124

    for (int k0 = 0; k0 < HIDDEN; k0 += BK) {
        #pragma unroll
        for (int it = 0; it < 2; it++) {
            int arow = ar0 + it * 64;
            int grow = rows[arow];
            float4 v = *reinterpret_cast<const float4*>(
                &A[(long long)grow * HIDDEN + k0 + ac4]);
            As[ac4 + 0][arow] = v.x;
            As[ac4 + 1][arow] = v.y;
            As[ac4 + 2][arow] = v.z;
            As[ac4 + 3][arow] = v.w;
        }
        #pragma unroll
        for (int it = 0; it < 2; it++) {
            int brow = br0 + it * 8;
            float4 v = *reinterpret_cast<const float4*>(
                &We[(long long)(k0 + brow) * HIDDEN + n0 + bc]);
            *reinterpret_cast<float4*>(&Bs[brow][bc]) = v;
        }
        __syncthreads();

        #pragma unroll
        for (int k = 0; k < BK; k++) {
            float a[8], b[8];
            #pragma unroll
            for (int i = 0; i < 8; i++) a[i] = As[k][tm + i];
            #pragma unroll
            for (int j = 0; j < 8; j++) b[j] = Bs[k][tn + j];
            #pragma unroll
            for (int i = 0; i < 8; i++)
                #pragma unroll
                for (int j = 0; j < 8; j++)
                    acc[i][j] = fmaf(a[i], b[j], acc[i][j]);
        }
        __syncthreads();
    }

    // Epilogue: bias + relu + scatter to original rows
    float bv[8];
    #pragma unroll
    for (int j = 0; j < 8; j++)
        bv[j] = bias[e * HIDDEN + n0 + tn + j];

    #pragma unroll
    for (int i = 0; i < 8; i++) {
        int mi = m0 + tm + i;
        if (mi < cnt) {
            int grow = rows[tm + i];
            float* outp = &Out[(long long)grow * HIDDEN + n0 + tn];
            float4 v0, v1;
            v0.x = fmaxf(acc[i][0] + bv[0], 0.f);
            v0.y = fmaxf(acc[i][1] + bv[1], 0.f);
            v0.z = fmaxf(acc[i][2] + bv[2], 0.f);
            v0.w = fmaxf(acc[i][3] + bv[3], 0.f);
            v1.x = fmaxf(acc[i][4] + bv[4], 0.f);
            v1.y = fmaxf(acc[i][5] + bv[5], 0.f);
            v1.z = fmaxf(acc[i][6] + bv[6], 0.f);
            v1.w = fmaxf(acc[i][7] + bv[7], 0.f);
            *reinterpret_cast<float4*>(outp + 0) = v0;
            *reinterpret_cast<float4*>(outp + 4) = v1;
        }
    }
}

extern "C" void kernel_launch(void* const* d_in, const int* in_sizes, int n_in,
                              void* d_out, int out_size) {
    const float* x      = (const float*)d_in[0];   // [BATCH, HIDDEN]
    const float* W1     = (const float*)d_in[1];   // [NUM_OPS, HIDDEN, HIDDEN]
    const float* b1     = (const float*)d_in[2];   // [NUM_OPS, HIDDEN]
    const float* W2     = (const float*)d_in[3];   // [NUM_OPS, HIDDEN, HIDDEN]
    const float* b2     = (const float*)d_in[4];   // [NUM_OPS, HIDDEN]
    const int*   chosen = (const int*)d_in[5];     // [BATCH]
    float* out = (float*)d_out;                    // [BATCH, HIDDEN]

    (void)in_sizes; (void)n_in; (void)out_size;

    // Reset + build per-expert row buckets (stream-ordered, graph-capturable)
    zero_counts_kernel<<<1, 32>>>();
    bucket_kernel<<<BATCH / 256, 256>>>(chosen);

    float* h_buf;
    cudaGetSymbolAddress((void**)&h_buf, g_h);

    dim3 grid(HIDDEN / BN, BATCH / BM, NUM_OPS);
    dim3 block(THREADS);

    // Layer 1: h = relu(x @ W1[e] + b1[e])  (only bucketed rows; inactive tiles exit)
    ffn_gemm_kernel<<<grid, block>>>(x, W1, b1, h_buf);
    // Layer 2: out = relu(h @ W2[e] + b2[e]), scattered to original rows
    ffn_gemm_kernel<<<grid, block>>>(h_buf, W2, b2, out);
}

// round 4
// speedup vs baseline: 4.1489x; 4.1489x over previous
#include <cuda_runtime.h>
#include <cstdint>

#define HIDDEN 2048
#define BATCH  16384
#define NUM_OPS 3

#define BM 128
#define BN 128
#define BK 32
#define NK (HIDDEN / BK)                  // 64
#define STAGES 3
#define A_STAGE_BYTES (BM * BK * 4)       // 16384
#define STAGE_BYTES ((BM + BN) * BK * 4)  // 32768
#define SMEM_BYTES (STAGES * STAGE_BYTES) // 98304

// ---- device scratch (static: allocation-free kernel_launch) ----
__device__ int   g_counts[NUM_OPS];
__device__ int   g_idx[NUM_OPS * BATCH];      // packed pos -> original row
__device__ int   g_pos[BATCH];                // original row -> packed pos
__device__ float g_xg[(size_t)NUM_OPS * BATCH * HIDDEN];   // gathered tf32-rounded x (packed)
__device__ float g_h [(size_t)NUM_OPS * BATCH * HIDDEN];   // layer-1 output (packed, tf32-rounded)
__device__ float g_Wt1[(size_t)NUM_OPS * HIDDEN * HIDDEN]; // W1^T: [e][n][h], tf32-rounded
__device__ float g_Wt2[(size_t)NUM_OPS * HIDDEN * HIDDEN]; // W2^T

// ---- PTX helpers (base-target legal) ----
__device__ __forceinline__ uint32_t smem_u32(const void* p) {
    uint32_t a;
    asm("{ .reg .u64 t; cvta.to.shared.u64 t, %1; cvt.u32.u64 %0, t; }" : "=r"(a) : "l"(p));
    return a;
}
__device__ __forceinline__ float rna_tf32(float x) {
    uint32_t u;
    asm("cvt.rna.tf32.f32 %0, %1;" : "=r"(u) : "f"(x));
    return __uint_as_float(u);
}
__device__ __forceinline__ void cp_async16(uint32_t saddr, const void* gaddr) {
    asm volatile("cp.async.cg.shared.global [%0], [%1], 16;" :: "r"(saddr), "l"(gaddr) : "memory");
}
__device__ __forceinline__ void cp_commit() {
    asm volatile("cp.async.commit_group;" ::: "memory");
}
template<int N> __device__ __forceinline__ void cp_wait() {
    asm volatile("cp.async.wait_group %0;" :: "n"(N) : "memory");
}
__device__ __forceinline__ float lds_f32(uint32_t addr) {
    float v;
    asm volatile("ld.shared.f32 %0, [%1];" : "=f"(v) : "r"(addr));
    return v;
}
__device__ __forceinline__ void mma_tf32(float* c, const float* a, float b0, float b1) {
    asm volatile(
        "mma.sync.aligned.m16n8k8.row.col.f32.tf32.tf32.f32 "
        "{%0,%1,%2,%3}, {%4,%5,%6,%7}, {%8,%9}, {%0,%1,%2,%3};"
        : "+f"(c[0]), "+f"(c[1]), "+f"(c[2]), "+f"(c[3])
        : "r"(__float_as_uint(a[0])), "r"(__float_as_uint(a[1])),
          "r"(__float_as_uint(a[2])), "r"(__float_as_uint(a[3])),
          "r"(__float_as_uint(b0)), "r"(__float_as_uint(b1)));
}

// ---- prep kernels ----
__global__ void zero_counts_kernel() {
    if (threadIdx.x < NUM_OPS) g_counts[threadIdx.x] = 0;
}
__global__ void bucket_kernel(const int* __restrict__ chosen) {
    int i = blockIdx.x * blockDim.x + threadIdx.x;
    if (i < BATCH) {
        int e = chosen[i];
        int pos = atomicAdd(&g_counts[e], 1);
        g_idx[e * BATCH + pos] = i;
        g_pos[i] = e * BATCH + pos;
    }
}
__global__ void gather_kernel(const float* __restrict__ x) {
    int row = blockIdx.x;
    int dst = g_pos[row];
    const float4* src = (const float4*)(x + (size_t)row * HIDDEN);
    float4* d = (float4*)(g_xg + (size_t)dst * HIDDEN);
    for (int j = threadIdx.x; j < HIDDEN / 4; j += blockDim.x) {
        float4 v = src[j];
        v.x = rna_tf32(v.x); v.y = rna_tf32(v.y);
        v.z = rna_tf32(v.z); v.w = rna_tf32(v.w);
        d[j] = v;
    }
}
// Wt[e][n][h] = rna(W[e][h][n])
__global__ void transpose_kernel(const float* __restrict__ W, float* __restrict__ Wt) {
    __shared__ float t[32][33];
    int e = blockIdx.z;
    const float* Win = W + (size_t)e * HIDDEN * HIDDEN;
    float* Wout = Wt + (size_t)e * HIDDEN * HIDDEN;
    int n0 = blockIdx.x * 32, h0 = blockIdx.y * 32;
    #pragma unroll
    for (int i = 0; i < 4; i++)
        t[threadIdx.y + i * 8][threadIdx.x] =
            rna_tf32(Win[(size_t)(h0 + threadIdx.y + i * 8) * HIDDEN + n0 + threadIdx.x]);
    __syncthreads();
    #pragma unroll
    for (int i = 0; i < 4; i++)
        Wout[(size_t)(n0 + threadIdx.y + i * 8) * HIDDEN + h0 + threadIdx.x] =
            t[threadIdx.x][threadIdx.y + i * 8];
}

// ---- tf32 mma.sync GEMM ----
// D[m, n] = relu( sum_k A[m, k] * Wt[e][n][k] + bias[e][n] )
template<bool ROUND, bool SCATTER>
__global__ void __launch_bounds__(256, 2)
gemm_mma_kernel(const float* __restrict__ A,
                const float* __restrict__ Wt,
                const float* __restrict__ bias,
                float* __restrict__ Out)
{
    const int e   = blockIdx.z;
    const int cnt = g_counts[e];
    const int m0  = blockIdx.y * BM;
    if (m0 >= cnt) return;
    const int n0  = blockIdx.x * BN;

    extern __shared__ char smem[];
    const uint32_t sbase = smem_u32(smem);

    const int tid  = threadIdx.x;
    const int lane = tid & 31;
    const int wid  = tid >> 5;
    const int wm   = wid >> 2;        // 0..1  (64-row half of tile)
    const int wn   = wid & 3;         // 0..3  (32-col quarter)

    const float* Abase = A + (size_t)(e * BATCH + m0) * HIDDEN;
    const float* Bbase = Wt + (size_t)e * HIDDEN * HIDDEN + (size_t)n0 * HIDDEN;

    // fragment row/col invariants (m16n8k8 tf32 layout)
    const int fr = lane >> 2;         // 0..7  fragment row (A row / B n)
    const int fc = lane & 3;          // 0..3  fragment col (k within k8)
    const int a_r0 = wm * 64 + fr;    // + i*16 (+8 for a1/a3)
    const int b_r0 = wn * 32 + fr;    // + j*8

    float acc[4][4][4];
    #pragma unroll
    for (int i = 0; i < 4; i++)
        #pragma unroll
        for (int j = 0; j < 4; j++)
            #pragma unroll
            for (int q = 0; q < 4; q++) acc[i][j][q] = 0.f;

    // smem addr of element [r][k] in a swizzled tile: r*128B, 16B-unit (k>>2)^(r&7)
    auto saddr = [](uint32_t tilebase, int r, int kunit, int kin) -> uint32_t {
        return tilebase + (uint32_t)(r * 128) + (uint32_t)(((kunit ^ (r & 7)) << 4) + kin * 4);
    };

    // ---- stage loader: 1024 16B-chunks per matrix, 4 per thread ----
    auto load_stage = [&](int s, int kt) {
        const uint32_t sa = sbase + s * STAGE_BYTES;
        const uint32_t sb = sa + A_STAGE_BYTES;
        const int kcol = kt * BK;
        #pragma unroll
        for (int i = 0; i < 4; i++) {
            int lin  = tid + i * 256;
            int row  = lin >> 3;
            int unit = lin & 7;
            uint32_t soff = (uint32_t)(row * 128 + ((unit ^ (row & 7)) << 4));
            cp_async16(sa + soff, Abase + (size_t)row * HIDDEN + kcol + unit * 4);
            cp_async16(sb + soff, Bbase + (size_t)row * HIDDEN + kcol + unit * 4);
        }
        cp_commit();
    };

    // ---- compute one BK=32 stage: 4 k8-steps ----
    auto compute_stage = [&](int s) {
        const uint32_t sa = sbase + s * STAGE_BYTES;
        const uint32_t sb = sa + A_STAGE_BYTES;
        #pragma unroll
        for (int k8 = 0; k8 < 4; k8++) {
            const int u0 = k8 * 2, u1 = k8 * 2 + 1;   // 16B k-units for c and c+4
            float af[4][4], bf[4][2];
            #pragma unroll
            for (int i = 0; i < 4; i++) {
                int r0 = a_r0 + i * 16, r1 = r0 + 8;
                af[i][0] = lds_f32(saddr(sa, r0, u0, fc));
                af[i][1] = lds_f32(saddr(sa, r1, u0, fc));
                af[i][2] = lds_f32(saddr(sa, r0, u1, fc));
                af[i][3] = lds_f32(saddr(sa, r1, u1, fc));
            }
            #pragma unroll
            for (int j = 0; j < 4; j++) {
                int nr = b_r0 + j * 8;
                bf[j][0] = lds_f32(saddr(sb, nr, u0, fc));
                bf[j][1] = lds_f32(saddr(sb, nr, u1, fc));
            }
            #pragma unroll
            for (int i = 0; i < 4; i++)
                #pragma unroll
                for (int j = 0; j < 4; j++)
                    mma_tf32(acc[i][j], af[i], bf[j][0], bf[j][1]);
        }
    };

    // ---- pipeline ----
    load_stage(0, 0);
    load_stage(1, 1);

    int sidx = 0;
    for (int kt = 0; kt < NK; kt++) {
        if (kt + 2 < NK) {
            load_stage((kt + 2) % STAGES, kt + 2);
            cp_wait<2>();
        } else if (kt + 1 < NK) {
            cp_wait<1>();
        } else {
            cp_wait<0>();
        }
        __syncthreads();
        compute_stage(sidx);
        __syncthreads();
        sidx = (sidx + 1) % STAGES;
    }

    // ---- epilogue: bias + relu (+ tf32 round) + store ----
    float bv[4][2];
    #pragma unroll
    for (int j = 0; j < 4; j++) {
        int col = n0 + wn * 32 + j * 8 + 2 * fc;
        bv[j][0] = bias[e * HIDDEN + col];
        bv[j][1] = bias[e * HIDDEN + col + 1];
    }

    #pragma unroll
    for (int i = 0; i < 4; i++) {
        #pragma unroll
        for (int half = 0; half < 2; half++) {
            int rt = wm * 64 + i * 16 + half * 8 + fr;
            int m  = m0 + rt;
            if (m < cnt) {
                size_t orow = SCATTER ? (size_t)g_idx[e * BATCH + m]
                                      : (size_t)(e * BATCH + m);
                float* op = Out + orow * HIDDEN + n0 + wn * 32;
                #pragma unroll
                for (int j = 0; j < 4; j++) {
                    float v0 = fmaxf(acc[i][j][half * 2 + 0] + bv[j][0], 0.f);
                    float v1 = fmaxf(acc[i][j][half * 2 + 1] + bv[j][1], 0.f);
                    if (ROUND) { v0 = rna_tf32(v0); v1 = rna_tf32(v1); }
                    float2 v; v.x = v0; v.y = v1;
                    *reinterpret_cast<float2*>(op + j * 8 + 2 * fc) = v;
                }
            }
        }
    }
}

extern "C" void kernel_launch(void* const* d_in, const int* in_sizes, int n_in,
                              void* d_out, int out_size) {
    const float* x      = (const float*)d_in[0];
    const float* W1     = (const float*)d_in[1];
    const float* b1     = (const float*)d_in[2];
    const float* W2     = (const float*)d_in[3];
    const float* b2     = (const float*)d_in[4];
    const int*   chosen = (const int*)d_in[5];
    float* out = (float*)d_out;
    (void)in_sizes; (void)n_in; (void)out_size;

    void *p_xg, *p_h, *p_wt1, *p_wt2;
    cudaGetSymbolAddress(&p_xg,  g_xg);
    cudaGetSymbolAddress(&p_h,   g_h);
    cudaGetSymbolAddress(&p_wt1, g_Wt1);
    cudaGetSymbolAddress(&p_wt2, g_Wt2);

    cudaFuncSetAttribute(gemm_mma_kernel<true, false>,
                         cudaFuncAttributeMaxDynamicSharedMemorySize, SMEM_BYTES);
    cudaFuncSetAttribute(gemm_mma_kernel<false, true>,
                         cudaFuncAttributeMaxDynamicSharedMemorySize, SMEM_BYTES);

    // prep: buckets, gathered+rounded A, transposed+rounded weights
    zero_counts_kernel<<<1, 32>>>();
    bucket_kernel<<<BATCH / 256, 256>>>(chosen);
    gather_kernel<<<BATCH, 256>>>(x);
    dim3 tb(32, 8), tg(HIDDEN / 32, HIDDEN / 32, NUM_OPS);
    transpose_kernel<<<tg, tb>>>(W1, (float*)p_wt1);
    transpose_kernel<<<tg, tb>>>(W2, (float*)p_wt2);

    // GEMMs
    dim3 grid(HIDDEN / BN, BATCH / BM, NUM_OPS);
    gemm_mma_kernel<true,  false><<<grid, 256, SMEM_BYTES>>>(
        (const float*)p_xg, (const float*)p_wt1, b1, (float*)p_h);
    gemm_mma_kernel<false, true ><<<grid, 256, SMEM_BYTES>>>(
        (const float*)p_h, (const float*)p_wt2, b2, out);
}

// round 5
// speedup vs baseline: 4.3052x; 1.0377x over previous
#include <cuda_runtime.h>
#include <cstdint>

#define HIDDEN 2048
#define BATCH  16384
#define NUM_OPS 3

#define BM 128
#define BN 128
#define BK 32
#define NK (HIDDEN / BK)                  // 64
#define STAGES 3
#define A_STAGE_BYTES (BM * BK * 4)       // 16384
#define STAGE_BYTES ((BM + BN) * BK * 4)  // 32768
#define SMEM_BYTES (STAGES * STAGE_BYTES) // 98304
#define THREADS 128

// ---- device scratch (static: allocation-free kernel_launch) ----
__device__ int   g_counts[NUM_OPS];
__device__ int   g_idx[NUM_OPS * BATCH];
__device__ int   g_pos[BATCH];
// All matrices below are stored k-PERMUTED within each 8-float k-group:
// position p(k) = (k&~7) | ((k&3)<<1) | ((k>>2)&1)   (pairs k,k+4 adjacent)
__device__ float g_xg[(size_t)NUM_OPS * BATCH * HIDDEN];
__device__ float g_h [(size_t)NUM_OPS * BATCH * HIDDEN];
__device__ float g_Wt1[(size_t)NUM_OPS * HIDDEN * HIDDEN]; // [e][n][h] transposed
__device__ float g_Wt2[(size_t)NUM_OPS * HIDDEN * HIDDEN];

// ---- PTX helpers (base-target legal) ----
__device__ __forceinline__ uint32_t smem_u32(const void* p) {
    uint32_t a;
    asm("{ .reg .u64 t; cvta.to.shared.u64 t, %1; cvt.u32.u64 %0, t; }" : "=r"(a) : "l"(p));
    return a;
}
__device__ __forceinline__ float rna_tf32(float x) {
    uint32_t u;
    asm("cvt.rna.tf32.f32 %0, %1;" : "=r"(u) : "f"(x));
    return __uint_as_float(u);
}
__device__ __forceinline__ void cp_async16(uint32_t saddr, const void* gaddr) {
    asm volatile("cp.async.cg.shared.global [%0], [%1], 16;" :: "r"(saddr), "l"(gaddr) : "memory");
}
__device__ __forceinline__ void cp_commit() {
    asm volatile("cp.async.commit_group;" ::: "memory");
}
template<int N> __device__ __forceinline__ void cp_wait() {
    asm volatile("cp.async.wait_group %0;" :: "n"(N) : "memory");
}
__device__ __forceinline__ float2 lds_f32x2(uint32_t addr) {
    float2 v;
    asm volatile("ld.shared.v2.f32 {%0,%1}, [%2];" : "=f"(v.x), "=f"(v.y) : "r"(addr));
    return v;
}
__device__ __forceinline__ void mma_tf32(float* c, float a0, float a1, float a2, float a3,
                                         float b0, float b1) {
    asm volatile(
        "mma.sync.aligned.m16n8k8.row.col.f32.tf32.tf32.f32 "
        "{%0,%1,%2,%3}, {%4,%5,%6,%7}, {%8,%9}, {%0,%1,%2,%3};"
        : "+f"(c[0]), "+f"(c[1]), "+f"(c[2]), "+f"(c[3])
        : "r"(__float_as_uint(a0)), "r"(__float_as_uint(a1)),
          "r"(__float_as_uint(a2)), "r"(__float_as_uint(a3)),
          "r"(__float_as_uint(b0)), "r"(__float_as_uint(b1)));
}

// ---- prep kernels ----
__global__ void zero_counts_kernel() {
    if (threadIdx.x < NUM_OPS) g_counts[threadIdx.x] = 0;
}
__global__ void bucket_kernel(const int* __restrict__ chosen) {
    int i = blockIdx.x * blockDim.x + threadIdx.x;
    if (i < BATCH) {
        int e = chosen[i];
        int pos = atomicAdd(&g_counts[e], 1);
        g_idx[e * BATCH + pos] = i;
        g_pos[i] = e * BATCH + pos;
    }
}
// gather + rna round + k-permute: out group [k,k+4,k+1,k+5 | k+2,k+6,k+3,k+7]
__global__ void gather_kernel(const float* __restrict__ x) {
    int row = blockIdx.x;
    int dst = g_pos[row];
    const float4* src = (const float4*)(x + (size_t)row * HIDDEN);
    float4* d = (float4*)(g_xg + (size_t)dst * HIDDEN);
    int m = threadIdx.x;                   // 0..255, one 8-float group each
    float4 lo = src[2 * m], hi = src[2 * m + 1];
    float4 o0, o1;
    o0.x = rna_tf32(lo.x); o0.y = rna_tf32(hi.x);
    o0.z = rna_tf32(lo.y); o0.w = rna_tf32(hi.y);
    o1.x = rna_tf32(lo.z); o1.y = rna_tf32(hi.z);
    o1.z = rna_tf32(lo.w); o1.w = rna_tf32(hi.w);
    d[2 * m] = o0; d[2 * m + 1] = o1;
}
// Wt[e][n][perm(h)] = rna(W[e][h][n])
__global__ void transpose_kernel(const float* __restrict__ W, float* __restrict__ Wt) {
    __shared__ float t[32][33];
    int e = blockIdx.z;
    const float* Win = W + (size_t)e * HIDDEN * HIDDEN;
    float* Wout = Wt + (size_t)e * HIDDEN * HIDDEN;
    int n0 = blockIdx.x * 32, h0 = blockIdx.y * 32;
    int tx = threadIdx.x;
    #pragma unroll
    for (int i = 0; i < 4; i++)
        t[threadIdx.y + i * 8][tx] =
            rna_tf32(Win[(size_t)(h0 + threadIdx.y + i * 8) * HIDDEN + n0 + tx]);
    __syncthreads();
    int px = (tx & ~7) | ((tx & 3) << 1) | ((tx >> 2) & 1);   // k-permute within group of 8
    #pragma unroll
    for (int i = 0; i < 4; i++)
        Wout[(size_t)(n0 + threadIdx.y + i * 8) * HIDDEN + h0 + px] =
            t[tx][threadIdx.y + i * 8];
}

// ---- tf32 mma.sync GEMM, 64x64 warp tiles, v2 fragment loads ----
// PERM: permute output columns (when Out feeds the next GEMM as A)
template<bool ROUND, bool SCATTER, bool PERM>
__global__ void __launch_bounds__(THREADS, 2)
gemm_mma_kernel(const float* __restrict__ A,
                const float* __restrict__ Wt,
                const float* __restrict__ bias,
                float* __restrict__ Out)
{
    const int e   = blockIdx.z;
    const int cnt = g_counts[e];
    const int m0  = blockIdx.y * BM;
    if (m0 >= cnt) return;
    const int n0  = blockIdx.x * BN;

    extern __shared__ char smem[];
    const uint32_t sbase = smem_u32(smem);

    const int tid  = threadIdx.x;
    const int lane = tid & 31;
    const int wid  = tid >> 5;          // 0..3
    const int wm   = wid >> 1;          // 0..1 (64-row half)
    const int wn   = wid & 1;           // 0..1 (64-col half)

    const float* Abase = A + (size_t)(e * BATCH + m0) * HIDDEN;
    const float* Bbase = Wt + (size_t)e * HIDDEN * HIDDEN + (size_t)n0 * HIDDEN;

    const int fr = lane >> 2;           // 0..7
    const int fc = lane & 3;            // 0..3
    const int a_r0 = wm * 64 + fr;      // + i*16 (+8)
    const int b_r0 = wn * 64 + fr;      // + j*8

    float acc[4][8][4];
    #pragma unroll
    for (int i = 0; i < 4; i++)
        #pragma unroll
        for (int j = 0; j < 8; j++)
            #pragma unroll
            for (int q = 0; q < 4; q++) acc[i][j][q] = 0.f;

    // 8B-granular swizzled v2 address: row r, k8-group g, frag col fc
    auto vaddr = [](uint32_t tb, int r, int g, int fc_) -> uint32_t {
        return tb + (uint32_t)(r * 128) + (uint32_t)((((g * 4 + fc_) ^ ((r & 3) * 4)) << 3));
    };

    // ---- stage loader: 2048 16B chunks / 128 threads = 16 each ----
    auto load_stage = [&](int s, int kt) {
        const uint32_t sa = sbase + s * STAGE_BYTES;
        const uint32_t sb = sa + A_STAGE_BYTES;
        const int kcol = kt * BK;
        #pragma unroll
        for (int i = 0; i < 8; i++) {
            int lin = tid + i * THREADS;
            int row = lin >> 3;
            int q   = lin & 7;
            uint32_t soff = (uint32_t)(row * 128 + ((q ^ ((row & 3) * 2)) << 4));
            cp_async16(sa + soff, Abase + (size_t)row * HIDDEN + kcol + q * 4);
            cp_async16(sb + soff, Bbase + (size_t)row * HIDDEN + kcol + q * 4);
        }
        cp_commit();
    };

    // ---- compute one BK=32 stage ----
    auto compute_stage = [&](int s) {
        const uint32_t sa = sbase + s * STAGE_BYTES;
        const uint32_t sb = sa + A_STAGE_BYTES;
        #pragma unroll
        for (int g = 0; g < 4; g++) {
            float2 af0[4], af1[4], bf[8];
            #pragma unroll
            for (int i = 0; i < 4; i++) {
                af0[i] = lds_f32x2(vaddr(sa, a_r0 + i * 16,     g, fc));  // {a0, a2}
                af1[i] = lds_f32x2(vaddr(sa, a_r0 + i * 16 + 8, g, fc));  // {a1, a3}
            }
            #pragma unroll
            for (int j = 0; j < 8; j++)
                bf[j] = lds_f32x2(vaddr(sb, b_r0 + j * 8, g, fc));        // {b0, b1}
            #pragma unroll
            for (int i = 0; i < 4; i++)
                #pragma unroll
                for (int j = 0; j < 8; j++)
                    mma_tf32(acc[i][j], af0[i].x, af1[i].x, af0[i].y, af1[i].y,
                             bf[j].x, bf[j].y);
        }
    };

    // ---- pipeline ----
    load_stage(0, 0);
    load_stage(1, 1);

    int sidx = 0;
    for (int kt = 0; kt < NK; kt++) {
        if (kt + 2 < NK) {
            load_stage((kt + 2) % STAGES, kt + 2);
            cp_wait<2>();
        } else if (kt + 1 < NK) {
            cp_wait<1>();
        } else {
            cp_wait<0>();
        }
        __syncthreads();
        compute_stage(sidx);
        __syncthreads();
        sidx = (sidx + 1) % STAGES;
    }

    // ---- epilogue ----
    float bv[8][2];
    #pragma unroll
    for (int j = 0; j < 8; j++) {
        int col = n0 + wn * 64 + j * 8 + 2 * fc;
        bv[j][0] = bias[e * HIDDEN + col];
        bv[j][1] = bias[e * HIDDEN + col + 1];
    }

    #pragma unroll
    for (int i = 0; i < 4; i++) {
        #pragma unroll
        for (int half = 0; half < 2; half++) {
            int rt = wm * 64 + i * 16 + half * 8 + fr;
            int m  = m0 + rt;
            if (m < cnt) {
                size_t orow = SCATTER ? (size_t)g_idx[e * BATCH + m]
                                      : (size_t)(e * BATCH + m);
                float* op = Out + orow * HIDDEN;
                #pragma unroll
                for (int j = 0; j < 8; j++) {
                    float v0 = fmaxf(acc[i][j][half * 2 + 0] + bv[j][0], 0.f);
                    float v1 = fmaxf(acc[i][j][half * 2 + 1] + bv[j][1], 0.f);
                    if (ROUND) { v0 = rna_tf32(v0); v1 = rna_tf32(v1); }
                    int c0 = n0 + wn * 64 + j * 8 + 2 * fc;
                    if (PERM) {
                        int p0 = (c0 & ~7) | ((c0 & 3) << 1) | ((c0 >> 2) & 1);
                        int c1 = c0 + 1;
                        int p1 = (c1 & ~7) | ((c1 & 3) << 1) | ((c1 >> 2) & 1);
                        op[p0] = v0;
                        op[p1] = v1;
                    } else {
                        float2 v; v.x = v0; v.y = v1;
                        *reinterpret_cast<float2*>(op + c0) = v;
                    }
                }
            }
        }
    }
}

extern "C" void kernel_launch(void* const* d_in, const int* in_sizes, int n_in,
                              void* d_out, int out_size) {
    const float* x      = (const float*)d_in[0];
    const float* W1     = (const float*)d_in[1];
    const float* b1     = (const float*)d_in[2];
    const float* W2     = (const float*)d_in[3];
    const float* b2     = (const float*)d_in[4];
    const int*   chosen = (const int*)d_in[5];
    float* out = (float*)d_out;
    (void)in_sizes; (void)n_in; (void)out_size;

    void *p_xg, *p_h, *p_wt1, *p_wt2;
    cudaGetSymbolAddress(&p_xg,  g_xg);
    cudaGetSymbolAddress(&p_h,   g_h);
    cudaGetSymbolAddress(&p_wt1, g_Wt1);
    cudaGetSymbolAddress(&p_wt2, g_Wt2);

    cudaFuncSetAttribute(gemm_mma_kernel<true, false, true>,
                         cudaFuncAttributeMaxDynamicSharedMemorySize, SMEM_BYTES);
    cudaFuncSetAttribute(gemm_mma_kernel<false, true, false>,
                         cudaFuncAttributeMaxDynamicSharedMemorySize, SMEM_BYTES);

    zero_counts_kernel<<<1, 32>>>();
    bucket_kernel<<<BATCH / 256, 256>>>(chosen);
    gather_kernel<<<BATCH, 256>>>(x);
    dim3 tb(32, 8), tg(HIDDEN / 32, HIDDEN / 32, NUM_OPS);
    transpose_kernel<<<tg, tb>>>(W1, (float*)p_wt1);
    transpose_kernel<<<tg, tb>>>(W2, (float*)p_wt2);

    dim3 grid(HIDDEN / BN, BATCH / BM, NUM_OPS);
    // layer 1: h = relu(x@W1+b1), packed + k-permuted (feeds layer 2 as A)
    gemm_mma_kernel<true,  false, true ><<<grid, THREADS, SMEM_BYTES>>>(
        (const float*)p_xg, (const float*)p_wt1, b1, (float*)p_h);
    // layer 2: out = relu(h@W2+b2), scattered, logical column order
    gemm_mma_kernel<false, true,  false><<<grid, THREADS, SMEM_BYTES>>>(
        (const float*)p_h, (const float*)p_wt2, b2, out);
}

// round 6
// speedup vs baseline: 8.1453x; 1.8920x over previous
#include <cuda_runtime.h>
#include <cuda_fp16.h>
#include <cstdint>

#define HIDDEN 2048
#define BATCH  16384
#define NUM_OPS 3

#define BM 128
#define BN 128
#define BK 64
#define NK (HIDDEN / BK)                  // 32
#define STAGES 3
#define A_STAGE_BYTES (BM * BK * 2)       // 16384
#define STAGE_BYTES ((BM + BN) * BK * 2)  // 32768
#define SMEM_BYTES (STAGES * STAGE_BYTES) // 98304
#define THREADS 128

// ---- device scratch (static: allocation-free kernel_launch) ----
__device__ int    g_counts[NUM_OPS];
__device__ int    g_idx[NUM_OPS * BATCH];
__device__ int    g_pos[BATCH];
// fp16 matrices, k-dim PERMUTED at b32-unit granularity within 16-elem groups:
// unit u (= fp16 elems 2u,2u+1) stored at position p(u) = (u&~7) | ((u&3)<<1) | ((u>>2)&1)
__device__ __half g_xg[(size_t)NUM_OPS * BATCH * HIDDEN];
__device__ __half g_h [(size_t)NUM_OPS * BATCH * HIDDEN];
__device__ __half g_Wt1[(size_t)NUM_OPS * HIDDEN * HIDDEN]; // [e][n][h-perm]
__device__ __half g_Wt2[(size_t)NUM_OPS * HIDDEN * HIDDEN];

// ---- PTX helpers (base-target legal) ----
__device__ __forceinline__ uint32_t smem_u32(const void* p) {
    uint32_t a;
    asm("{ .reg .u64 t; cvta.to.shared.u64 t, %1; cvt.u32.u64 %0, t; }" : "=r"(a) : "l"(p));
    return a;
}
__device__ __forceinline__ void cp_async16(uint32_t saddr, const void* gaddr) {
    asm volatile("cp.async.cg.shared.global [%0], [%1], 16;" :: "r"(saddr), "l"(gaddr) : "memory");
}
__device__ __forceinline__ void cp_commit() {
    asm volatile("cp.async.commit_group;" ::: "memory");
}
template<int N> __device__ __forceinline__ void cp_wait() {
    asm volatile("cp.async.wait_group %0;" :: "n"(N) : "memory");
}
__device__ __forceinline__ uint2 lds_u32x2(uint32_t addr) {
    uint2 v;
    asm volatile("ld.shared.v2.b32 {%0,%1}, [%2];" : "=r"(v.x), "=r"(v.y) : "r"(addr));
    return v;
}
__device__ __forceinline__ void mma_f16(float* c, uint32_t a0, uint32_t a1,
                                        uint32_t a2, uint32_t a3,
                                        uint32_t b0, uint32_t b1) {
    asm volatile(
        "mma.sync.aligned.m16n8k16.row.col.f32.f16.f16.f32 "
        "{%0,%1,%2,%3}, {%4,%5,%6,%7}, {%8,%9}, {%0,%1,%2,%3};"
        : "+f"(c[0]), "+f"(c[1]), "+f"(c[2]), "+f"(c[3])
        : "r"(a0), "r"(a1), "r"(a2), "r"(a3), "r"(b0), "r"(b1));
}
__device__ __forceinline__ uint32_t h2bits(float lo, float hi) {
    __half2 h = __floats2half2_rn(lo, hi);
    return *reinterpret_cast<uint32_t*>(&h);
}

// ---- prep kernels ----
__global__ void zero_counts_kernel() {
    if (threadIdx.x < NUM_OPS) g_counts[threadIdx.x] = 0;
}
__global__ void bucket_kernel(const int* __restrict__ chosen) {
    int i = blockIdx.x * blockDim.x + threadIdx.x;
    if (i < BATCH) {
        int e = chosen[i];
        int pos = atomicAdd(&g_counts[e], 1);
        g_idx[e * BATCH + pos] = i;
        g_pos[i] = e * BATCH + pos;
    }
}
// gather row -> packed fp16, unit-permuted. thread = one 16-elem k-group.
__global__ void gather_kernel(const float* __restrict__ x) {
    int row = blockIdx.x;
    int dst = g_pos[row];
    int g = threadIdx.x;                    // 0..127
    const float4* src = (const float4*)(x + (size_t)row * HIDDEN + g * 16);
    float4 v0 = src[0], v1 = src[1], v2 = src[2], v3 = src[3];
    uint32_t u[8];
    u[0] = h2bits(v0.x, v0.y); u[1] = h2bits(v0.z, v0.w);
    u[2] = h2bits(v1.x, v1.y); u[3] = h2bits(v1.z, v1.w);
    u[4] = h2bits(v2.x, v2.y); u[5] = h2bits(v2.z, v2.w);
    u[6] = h2bits(v3.x, v3.y); u[7] = h2bits(v3.z, v3.w);
    // permuted order: positions [u0,u4,u1,u5 | u2,u6,u3,u7]
    uint4 w0 = make_uint4(u[0], u[4], u[1], u[5]);
    uint4 w1 = make_uint4(u[2], u[6], u[3], u[7]);
    uint4* d = (uint4*)(g_xg + (size_t)dst * HIDDEN + g * 16);
    d[0] = w0; d[1] = w1;
}
// Wt[e][n][perm-units of h] = fp16(W[e][h][n])
__global__ void transpose_kernel(const float* __restrict__ W, __half* __restrict__ Wt) {
    __shared__ float t[32][33];
    int e = blockIdx.z;
    const float* Win = W + (size_t)e * HIDDEN * HIDDEN;
    __half* Wout = Wt + (size_t)e * HIDDEN * HIDDEN;
    int n0 = blockIdx.x * 32, h0 = blockIdx.y * 32;
    int tx = threadIdx.x, ty = threadIdx.y;
    #pragma unroll
    for (int i = 0; i < 4; i++)
        t[ty + i * 8][tx] = Win[(size_t)(h0 + ty + i * 8) * HIDDEN + n0 + tx];
    __syncthreads();
    // write: 16 units (32 h) per n-row; threads: u = tx&15, n covered by (tx>>4, ty, i)
    int u = tx & 15;
    int hu = (h0 >> 1) + u;
    int p  = (hu & ~7) | ((hu & 3) << 1) | ((hu >> 2) & 1);
    int nb = ty + (tx >> 4) * 8;
    #pragma unroll
    for (int i = 0; i < 2; i++) {
        int nl = nb + i * 16;
        __half2 h = __floats2half2_rn(t[2 * u][nl], t[2 * u + 1][nl]);
        *((__half2*)(Wout + (size_t)(n0 + nl) * HIDDEN) + p) = h;
    }
}

// ---- fp16 m16n8k16 GEMM, 64x64 warp tiles ----
// FIRST: Out = __half* packed+permuted (feeds layer 2). else: Out = float* scattered.
template<bool FIRST>
__global__ void __launch_bounds__(THREADS, 2)
gemm_mma_kernel(const __half* __restrict__ A,
                const __half* __restrict__ Wt,
                const float* __restrict__ bias,
                void* __restrict__ OutV)
{
    const int e   = blockIdx.z;
    const int cnt = g_counts[e];
    const int m0  = blockIdx.y * BM;
    if (m0 >= cnt) return;
    const int n0  = blockIdx.x * BN;

    extern __shared__ char smem[];
    const uint32_t sbase = smem_u32(smem);

    const int tid  = threadIdx.x;
    const int lane = tid & 31;
    const int wid  = tid >> 5;
    const int wm   = wid >> 1;
    const int wn   = wid & 1;

    const __half* Abase = A + (size_t)(e * BATCH + m0) * HIDDEN;
    const __half* Bbase = Wt + (size_t)e * HIDDEN * HIDDEN + (size_t)n0 * HIDDEN;

    const int fr = lane >> 2;
    const int fc = lane & 3;
    const int a_r0 = wm * 64 + fr;
    const int b_r0 = wn * 64 + fr;

    float acc[4][8][4];
    #pragma unroll
    for (int i = 0; i < 4; i++)
        #pragma unroll
        for (int j = 0; j < 8; j++)
            #pragma unroll
            for (int q = 0; q < 4; q++) acc[i][j][q] = 0.f;

    // 8B slot address: row r (128B rows), k16-group g, frag col fc
    auto vaddr = [](uint32_t tb, int r, int g, int fc_) -> uint32_t {
        return tb + (uint32_t)(r * 128) + (uint32_t)((((g * 4 + fc_) ^ ((r & 3) * 4)) << 3));
    };

    // ---- stage loader: 2048 16B chunks / 128 threads = 16 per thread ----
    auto load_stage = [&](int s, int kt) {
        const uint32_t sa = sbase + s * STAGE_BYTES;
        const uint32_t sb = sa + A_STAGE_BYTES;
        const int kcol = kt * BK;
        #pragma unroll
        for (int i = 0; i < 8; i++) {
            int lin = tid + i * THREADS;
            int row = lin >> 3;
            int q   = lin & 7;
            uint32_t soff = (uint32_t)(row * 128 + ((q ^ ((row & 3) * 2)) << 4));
            cp_async16(sa + soff, Abase + (size_t)row * HIDDEN + kcol + q * 8);
            cp_async16(sb + soff, Bbase + (size_t)row * HIDDEN + kcol + q * 8);
        }
        cp_commit();
    };

    // ---- compute one BK=64 stage: 4 k16-groups ----
    auto compute_stage = [&](int s) {
        const uint32_t sa = sbase + s * STAGE_BYTES;
        const uint32_t sb = sa + A_STAGE_BYTES;
        #pragma unroll
        for (int g = 0; g < 4; g++) {
            uint2 alo[4], ahi[4], bf[8];
            #pragma unroll
            for (int i = 0; i < 4; i++) {
                alo[i] = lds_u32x2(vaddr(sa, a_r0 + i * 16,     g, fc));  // {a0, a2}
                ahi[i] = lds_u32x2(vaddr(sa, a_r0 + i * 16 + 8, g, fc));  // {a1, a3}
            }
            #pragma unroll
            for (int j = 0; j < 8; j++)
                bf[j] = lds_u32x2(vaddr(sb, b_r0 + j * 8, g, fc));        // {b0, b1}
            #pragma unroll
            for (int i = 0; i < 4; i++)
                #pragma unroll
                for (int j = 0; j < 8; j++)
                    mma_f16(acc[i][j], alo[i].x, ahi[i].x, alo[i].y, ahi[i].y,
                            bf[j].x, bf[j].y);
        }
    };

    // ---- pipeline ----
    load_stage(0, 0);
    load_stage(1, 1);

    int sidx = 0;
    for (int kt = 0; kt < NK; kt++) {
        if (kt + 2 < NK) {
            load_stage((kt + 2) % STAGES, kt + 2);
            cp_wait<2>();
        } else if (kt + 1 < NK) {
            cp_wait<1>();
        } else {
            cp_wait<0>();
        }
        __syncthreads();
        compute_stage(sidx);
        __syncthreads();
        sidx = (sidx + 1) % STAGES;
    }

    // ---- epilogue ----
    float bv[8][2];
    #pragma unroll
    for (int j = 0; j < 8; j++) {
        int col = n0 + wn * 64 + j * 8 + 2 * fc;
        bv[j][0] = bias[e * HIDDEN + col];
        bv[j][1] = bias[e * HIDDEN + col + 1];
    }

    #pragma unroll
    for (int i = 0; i < 4; i++) {
        #pragma unroll
        for (int half = 0; half < 2; half++) {
            int rt = wm * 64 + i * 16 + half * 8 + fr;
            int m  = m0 + rt;
            if (m < cnt) {
                if (FIRST) {
                    // packed fp16, unit-permuted columns
                    __half* op = (__half*)OutV + (size_t)(e * BATCH + m) * HIDDEN;
                    const int ubase = (n0 + wn * 64) >> 1;   // multiple of 32
                    #pragma unroll
                    for (int j2 = 0; j2 < 4; j2++) {
                        float v0e = fmaxf(acc[i][2 * j2][half * 2 + 0] + bv[2 * j2][0], 0.f);
                        float v1e = fmaxf(acc[i][2 * j2][half * 2 + 1] + bv[2 * j2][1], 0.f);
                        float v0o = fmaxf(acc[i][2 * j2 + 1][half * 2 + 0] + bv[2 * j2 + 1][0], 0.f);
                        float v1o = fmaxf(acc[i][2 * j2 + 1][half * 2 + 1] + bv[2 * j2 + 1][1], 0.f);
                        uint2 st;
                        st.x = h2bits(v0e, v1e);   // unit for j even -> position p
                        st.y = h2bits(v0o, v1o);   // unit for j odd  -> position p+1
                        int p = ubase + j2 * 8 + (fc << 1);
                        *reinterpret_cast<uint2*>((__half2*)op + p) = st;
                    }
                } else {
                    size_t orow = (size_t)g_idx[e * BATCH + m];
                    float* op = (float*)OutV + orow * HIDDEN;
                    #pragma unroll
                    for (int j = 0; j < 8; j++) {
                        float v0 = fmaxf(acc[i][j][half * 2 + 0] + bv[j][0], 0.f);
                        float v1 = fmaxf(acc[i][j][half * 2 + 1] + bv[j][1], 0.f);
                        float2 v; v.x = v0; v.y = v1;
                        *reinterpret_cast<float2*>(op + n0 + wn * 64 + j * 8 + 2 * fc) = v;
                    }
                }
            }
        }
    }
}

extern "C" void kernel_launch(void* const* d_in, const int* in_sizes, int n_in,
                              void* d_out, int out_size) {
    const float* x      = (const float*)d_in[0];
    const float* W1     = (const float*)d_in[1];
    const float* b1     = (const float*)d_in[2];
    const float* W2     = (const float*)d_in[3];
    const float* b2     = (const float*)d_in[4];
    const int*   chosen = (const int*)d_in[5];
    float* out = (float*)d_out;
    (void)in_sizes; (void)n_in; (void)out_size;

    void *p_xg, *p_h, *p_wt1, *p_wt2;
    cudaGetSymbolAddress(&p_xg,  g_xg);
    cudaGetSymbolAddress(&p_h,   g_h);
    cudaGetSymbolAddress(&p_wt1, g_Wt1);
    cudaGetSymbolAddress(&p_wt2, g_Wt2);

    cudaFuncSetAttribute(gemm_mma_kernel<true>,
                         cudaFuncAttributeMaxDynamicSharedMemorySize, SMEM_BYTES);
    cudaFuncSetAttribute(gemm_mma_kernel<false>,
                         cudaFuncAttributeMaxDynamicSharedMemorySize, SMEM_BYTES);

    zero_counts_kernel<<<1, 32>>>();
    bucket_kernel<<<BATCH / 256, 256>>>(chosen);
    gather_kernel<<<BATCH, 128>>>(x);
    dim3 tb(32, 8), tg(HIDDEN / 32, HIDDEN / 32, NUM_OPS);
    transpose_kernel<<<tg, tb>>>(W1, (__half*)p_wt1);
    transpose_kernel<<<tg, tb>>>(W2, (__half*)p_wt2);

    dim3 grid(HIDDEN / BN, BATCH / BM, NUM_OPS);
    gemm_mma_kernel<true ><<<grid, THREADS, SMEM_BYTES>>>(
        (const __half*)p_xg, (const __half*)p_wt1, b1, p_h);
    gemm_mma_kernel<false><<<grid, THREADS, SMEM_BYTES>>>(
        (const __half*)p_h, (const __half*)p_wt2, b2, out);
}